// round 3
// baseline (speedup 1.0000x reference)
#include <cuda_runtime.h>
#include <cuda_bf16.h>
#include <math.h>

// WarpTranspose: adjoint of bilinear warp (flow-guided bilinear scatter-add).
// grad_out: [B,H,W,C] f32, u: [B,H,W,2] f32 (dx,dy), out: [B,H,W,C] f32.
//
// Layout: 8 threads per source pixel. The two x-corners (y,x0),(y,x0+1) form a
// contiguous 128B region (2 pixels x 16ch x 4B). Lane j in [0,8) owns 16B chunk
// j of that region; left half (j<4) gets weight (1-wx), right half (j>=4) gets
// wx. Each thread issues 2 float4 atomicAdds (row y0, row y1), so a warp's
// row-RED covers whole 128B regions in ONE instruction -> ~2x fewer L1tex
// atomic wavefronts than the 4-corner/64B formulation.

#define H_DIM 512
#define W_DIM 512
#define C_DIM 16

__global__ void __launch_bounds__(256)
warp_transpose_scatter(const float* __restrict__ grad_out,
                       const float* __restrict__ u,
                       float* __restrict__ out,
                       int total_threads) {
    int gid = blockIdx.x * blockDim.x + threadIdx.x;
    if (gid >= total_threads) return;

    const int j = gid & 7;       // chunk lane within the 128B row-region
    const int p = gid >> 3;      // pixel index: ((b*H + y)*W + x)

    const int x = p & (W_DIM - 1);
    const int y = (p >> 9) & (H_DIM - 1);

    // flow (broadcast across the 8 lanes of this pixel)
    const float2 uv = __ldg((const float2*)(u + 2 * (size_t)p));
    const float gx = (float)x + uv.x;
    const float gy = (float)y + uv.y;

    const float x0f = floorf(gx);
    const float y0f = floorf(gy);
    const float wx = gx - x0f;
    const float wy = gy - y0f;
    const int x0 = (int)x0f;
    const int y0 = (int)y0f;

    // this lane's grad quad: lanes j and j+4 read the same 16B (hw dedups)
    const float4 g = __ldg((const float4*)(grad_out + (size_t)p * C_DIM + (j & 3) * 4));

    // x-weight select: left half of region -> (1-wx), right half -> wx
    const float wxs = (j >= 4) ? wx : (1.0f - wx);
    const float w0 = (1.0f - wy) * wxs;   // row y0
    const float w1 = wy * wxs;            // row y1

    // validity
    const int xi = x0 + (j >> 2);                       // this lane's target x
    const bool vx  = ((unsigned)xi < (unsigned)W_DIM);
    const bool vy0 = ((unsigned)y0 < (unsigned)H_DIM);
    const bool vy1 = ((unsigned)(y0 + 1) < (unsigned)H_DIM);

    // region base for row y0: pixel (b, y0, x0), chunk j
    // index = (p + (y0-y)*W + (x0-x)) * C + 4*j   (stays within batch image)
    const long long rel = (long long)(y0 - y) * W_DIM + (x0 - x);
    float* addr0 = out + ((long long)p + rel) * C_DIM + 4 * j;
    float* addr1 = addr0 + (long long)W_DIM * C_DIM;

    if (vx & vy0) {
        float4 v = make_float4(g.x * w0, g.y * w0, g.z * w0, g.w * w0);
        atomicAdd((float4*)addr0, v);
    }
    if (vx & vy1) {
        float4 v = make_float4(g.x * w1, g.y * w1, g.z * w1, g.w * w1);
        atomicAdd((float4*)addr1, v);
    }
}

extern "C" void kernel_launch(void* const* d_in, const int* in_sizes, int n_in,
                              void* d_out, int out_size) {
    const float* grad_out = (const float*)d_in[0];
    const float* u        = (const float*)d_in[1];
    float* out = (float*)d_out;

    const int B = in_sizes[1] / (H_DIM * W_DIM * 2);
    const int total_pixels = B * H_DIM * W_DIM;
    const int total_threads = total_pixels * 8;

    // zero the (poisoned) output — legal graph node, no allocation
    cudaMemsetAsync(d_out, 0, (size_t)out_size * sizeof(float), 0);

    const int block = 256;
    const int grid = (total_threads + block - 1) / block;
    warp_transpose_scatter<<<grid, block>>>(grad_out, u, out, total_threads);
}